// round 3
// baseline (speedup 1.0000x reference)
#include <cuda_runtime.h>
#include <cub/cub.cuh>

// Defeat --use_fast_math's expf -> __expf macro so expf = accurate libdevice
// __nv_expf, matching XLA's f32 exp bit-for-bit.
#ifdef expf
#undef expf
#endif

#define NB      4        // batch
#define NP      34125    // priors
#define NSEL    5000     // NMS_TOP_K
#define TOPK    750
#define NW      79       // ceil(NSEL/64)
#define CONF_T  0.05f
#define NMS_T   0.3f

#define NMS_THREADS 1024
#define SLOTS 5          // ceil(NSEL / NMS_THREADS)

// ---------------- static device scratch (no allocations allowed) ------------
__device__ unsigned long long g_keys_in [NB * NP];
__device__ unsigned int       g_vals_in [NB * NP];
__device__ unsigned long long g_keys_out[NB * NP];
__device__ unsigned int       g_vals_out[NB * NP];

__device__ float g_bx1[NB * NSEL];
__device__ float g_by1[NB * NSEL];
__device__ float g_bx2[NB * NSEL];
__device__ float g_by2[NB * NSEL];
__device__ float g_sc [NB * NSEL];

__device__ unsigned char g_temp[1u << 24];   // cub temp, 16 MB

// ---------------- helpers ----------------------------------------------------

__device__ __forceinline__ unsigned int f2sortable(float f) {
    unsigned int b = __float_as_uint(f);
    return (b & 0x80000000u) ? ~b : (b | 0x80000000u);
}
__device__ __forceinline__ float sortable2f(unsigned int u) {
    return __uint_as_float((u & 0x80000000u) ? (u & 0x7fffffffu) : ~u);
}

// ---------------- kernels ----------------------------------------------------

// Build 64-bit composite keys: high 2 bits = (3-img) so descending sort puts
// img 0 first; low 32 bits = monotonic float mapping of thresholded score.
__global__ void k_build(const float* __restrict__ conf) {
    int i = blockIdx.x * blockDim.x + threadIdx.x;
    if (i >= NB * NP) return;
    float c = conf[2 * i + 1];                 // class-1 score
    float s = (c > CONF_T) ? c : -1e30f;
    int img = i / NP;
    g_keys_in[i] = ((unsigned long long)(3 - img) << 32) | (unsigned long long)f2sortable(s);
    g_vals_in[i] = (unsigned int)(i % NP);
}

__global__ void k_gather(const float* __restrict__ loc,
                         const float* __restrict__ prior) {
    int t = blockIdx.x * blockDim.x + threadIdx.x;
    if (t >= NB * NSEL) return;
    int img = t / NSEL, j = t % NSEL;
    unsigned long long key = g_keys_out[img * NP + j];
    unsigned int p = g_vals_out[img * NP + j];
    g_sc[t] = sortable2f((unsigned int)key);

    const float* l  = loc   + ((size_t)img * NP + p) * 4;
    const float* pr = prior + (size_t)p * 4;
    float lx = l[0],  ly = l[1],  lw = l[2],  lh = l[3];
    float px = pr[0], py = pr[1], pw = pr[2], ph = pr[3];

    float cx = __fadd_rn(px, __fmul_rn(__fmul_rn(lx, 0.1f), pw));
    float cy = __fadd_rn(py, __fmul_rn(__fmul_rn(ly, 0.1f), ph));
    float w  = __fmul_rn(pw, expf(__fmul_rn(lw, 0.2f)));
    float h  = __fmul_rn(ph, expf(__fmul_rn(lh, 0.2f)));
    float x1 = __fsub_rn(cx, __fmul_rn(w, 0.5f));
    float y1 = __fsub_rn(cy, __fmul_rn(h, 0.5f));
    float x2 = __fadd_rn(x1, w);
    float y2 = __fadd_rn(y1, h);
    g_bx1[t] = x1; g_by1[t] = y1; g_bx2[t] = x2; g_by2[t] = y2;
}

__global__ void k_zero(float* __restrict__ out, int n) {
    int i = blockIdx.x * blockDim.x + threadIdx.x;
    if (i < n) out[i] = 0.0f;
}

// One block per image. Candidates register-resident (SLOTS per thread),
// suppression bitmap in shared memory. Greedy order == reference scan order;
// early exit at TOPK kept (reference drops rank >= TOPK via mode='drop').
__global__ __launch_bounds__(NMS_THREADS, 1)
void k_nms(float* __restrict__ out) {
    const int img = blockIdx.x;
    const int t   = threadIdx.x;

    __shared__ unsigned long long s_mask[NW];
    __shared__ float s_b[5];   // kept box broadcast: x1,y1,x2,y2,area

    // init mask: zero, with tail bits (j >= NSEL) pre-suppressed
    for (int w = t; w < NW; w += NMS_THREADS) {
        unsigned long long m = 0ull;
        int base = w * 64;
        if (base + 64 > NSEL) {
            for (int b = 0; b < 64; b++)
                if (base + b >= NSEL) m |= (1ull << b);
        }
        s_mask[w] = m;
    }

    // load candidates into registers
    float cx1[SLOTS], cy1[SLOTS], cx2[SLOTS], cy2[SLOTS], car[SLOTS], csc[SLOTS];
    unsigned int dead = 0;   // bit s: candidate slot s suppressed/invalid/consumed
#pragma unroll
    for (int s = 0; s < SLOTS; s++) {
        int j = s * NMS_THREADS + t;
        if (j < NSEL) {
            int o = img * NSEL + j;
            float x1 = g_bx1[o], y1 = g_by1[o], x2 = g_bx2[o], y2 = g_by2[o];
            cx1[s] = x1; cy1[s] = y1; cx2[s] = x2; cy2[s] = y2;
            car[s] = __fmul_rn(__fsub_rn(x2, x1), __fsub_rn(y2, y1));
            float sc = g_sc[o];
            csc[s] = sc;
            if (!(sc > CONF_T)) {   // sorted desc: invalids are a suffix; mark skip
                dead |= (1u << s);
                atomicOr(&s_mask[j >> 6], 1ull << (j & 63));
            }
        } else {
            dead |= (1u << s);
        }
    }
    __syncthreads();

    int cur = -1;   // last consumed index
    for (int rank = 0; rank < TOPK; rank++) {
        // --- redundant scan: every thread finds the same next-unsuppressed k
        int w = (cur + 1) >> 6;
        int b = (cur + 1) & 63;
        unsigned long long m = ~s_mask[w] & (~0ull << b);
        while (m == 0ull) {
            if (++w >= NW) break;
            m = ~s_mask[w];
        }
        int k = (w >= NW) ? NSEL : (w * 64 + __ffsll((long long)m) - 1);
        if (k >= NSEL) break;
        cur = k;

        // owner publishes the kept box + writes the output row
        if (t == (k & (NMS_THREADS - 1))) {
            int s = k / NMS_THREADS;
            s_b[0] = cx1[s]; s_b[1] = cy1[s]; s_b[2] = cx2[s]; s_b[3] = cy2[s];
            s_b[4] = car[s];
            float* row = out + ((size_t)(img * 2 + 1) * TOPK + rank) * 5;
            row[0] = csc[s];
            row[1] = cx1[s]; row[2] = cy1[s]; row[3] = cx2[s]; row[4] = cy2[s];
        }
        __syncthreads();   // bcast visible

        float kx1 = s_b[0], ky1 = s_b[1], kx2 = s_b[2], ky2 = s_b[3], ka = s_b[4];
#pragma unroll
        for (int s = 0; s < SLOTS; s++) {
            if (dead & (1u << s)) continue;
            int j = s * NMS_THREADS + t;
            if (j == k) {             // consume kept box
                dead |= (1u << s);
                atomicOr(&s_mask[j >> 6], 1ull << (j & 63));
                continue;
            }
            if (j < k) continue;      // can't happen (already consumed), guard
            float iw = fmaxf(__fsub_rn(fminf(kx2, cx2[s]), fmaxf(kx1, cx1[s])), 0.0f);
            float ih = fmaxf(__fsub_rn(fminf(ky2, cy2[s]), fmaxf(ky1, cy1[s])), 0.0f);
            float inter = __fmul_rn(iw, ih);
            float den   = __fsub_rn(__fadd_rn(ka, car[s]), inter);
            float iou   = __fdiv_rn(inter, den);
            if (iou > NMS_T) {
                dead |= (1u << s);
                atomicOr(&s_mask[j >> 6], 1ull << (j & 63));
            }
        }
        __syncthreads();   // mask updates visible before next scan
    }
}

// ---------------- launch ------------------------------------------------------

extern "C" void kernel_launch(void* const* d_in, const int* in_sizes, int n_in,
                              void* d_out, int out_size) {
    const float* loc   = (const float*)d_in[0];
    const float* conf  = (const float*)d_in[1];
    const float* prior = (const float*)d_in[2];
    float* out = (float*)d_out;

    void *keys_in_p, *vals_in_p, *keys_out_p, *vals_out_p, *temp_p;
    cudaGetSymbolAddress(&keys_in_p,  g_keys_in);
    cudaGetSymbolAddress(&vals_in_p,  g_vals_in);
    cudaGetSymbolAddress(&keys_out_p, g_keys_out);
    cudaGetSymbolAddress(&vals_out_p, g_vals_out);
    cudaGetSymbolAddress(&temp_p,     g_temp);

    k_build<<<(NB * NP + 255) / 256, 256>>>(conf);

    size_t tmp_bytes = 0;
    cub::DeviceRadixSort::SortPairsDescending(
        nullptr, tmp_bytes,
        (const unsigned long long*)keys_in_p, (unsigned long long*)keys_out_p,
        (const unsigned int*)vals_in_p,       (unsigned int*)vals_out_p,
        NB * NP, 0, 34, (cudaStream_t)0);
    if (tmp_bytes > (size_t)(1u << 24)) tmp_bytes = (size_t)(1u << 24);
    cub::DeviceRadixSort::SortPairsDescending(
        temp_p, tmp_bytes,
        (const unsigned long long*)keys_in_p, (unsigned long long*)keys_out_p,
        (const unsigned int*)vals_in_p,       (unsigned int*)vals_out_p,
        NB * NP, 0, 34, (cudaStream_t)0);

    k_gather<<<(NB * NSEL + 255) / 256, 256>>>(loc, prior);

    k_zero<<<(out_size + 255) / 256, 256>>>(out, out_size);
    k_nms<<<NB, NMS_THREADS>>>(out);
}